// round 4
// baseline (speedup 1.0000x reference)
#include <cuda_runtime.h>
#include <math.h>

#define BATCH 16384
#define NS 26
#define ND 13
#define EMB 128
#define KDIM 3328   // NS * EMB
#define HID 256
#define VOCAB 4823

// Scratch (device globals; no allocations allowed)
__device__ float g_P[(size_t)NS * VOCAB * HID];   // 26*4823*256 floats = 128.4 MB
__device__ float g_h1[BATCH * HID];
__device__ float g_h2[BATCH * HID];
__device__ float g_y12[BATCH];

// ---------------------------------------------------------------------------
// Kernel 1: first + second order FM terms, fused per sample.
// One block (128 threads) per sample; emb2 table (2.47 MB) is L2-resident.
// ---------------------------------------------------------------------------
__global__ void fm_kernel(const float* __restrict__ dense,
                          const int*   __restrict__ sparse,
                          const float* __restrict__ emb1,
                          const float* __restrict__ emb2,
                          const float* __restrict__ fm_w)
{
    const int i   = blockIdx.x;
    const int tid = threadIdx.x;
    __shared__ int   sidx[NS];
    __shared__ float wsum[4];

    if (tid < NS) sidx[tid] = sparse[i * NS + tid];
    __syncthreads();

    float s = 0.f, ss = 0.f;
#pragma unroll
    for (int f = 0; f < NS; f++) {
        const float v = __ldg(emb2 + (size_t)sidx[f] * EMB + tid);
        s += v; ss += v * v;
    }
    float val = 0.5f * (s * s - ss);               // second-order contribution
    if (tid < NS) val += __ldg(emb1 + sidx[tid]);  // first-order sparse
    if (tid < ND) val += dense[i * ND + tid] * fm_w[tid];  // first-order dense

#pragma unroll
    for (int off = 16; off; off >>= 1)
        val += __shfl_down_sync(0xffffffffu, val, off);
    if ((tid & 31) == 0) wsum[tid >> 5] = val;
    __syncthreads();
    if (tid == 0) g_y12[i] = wsum[0] + wsum[1] + wsum[2] + wsum[3];
}

// ---------------------------------------------------------------------------
// Kernel 2: precompute P[f][v][n] = sum_e emb2[v,e] * w1[n, f*128+e]
// 26 independent [4823,128]@[128,256] GEMMs (one per field, blockIdx.z).
// Tile 128(M=v) x 128(N=n), BK=16, DOUBLE-BUFFERED smem (one sync/tile):
//   LDG(t+1) -> compute(t) -> STS(t+1) -> sync.  Global latency hidden by
// the 1024-FMA/thread compute phase; barrier count halved vs 2-sync version.
// ---------------------------------------------------------------------------
__global__ __launch_bounds__(256, 2)
void precompute_P_kernel(const float* __restrict__ emb2,
                         const float* __restrict__ w1)
{
    __shared__ float As[2][16][128];
    __shared__ float Bs[2][16][128];

    const int tid = threadIdx.x;
    const int f   = blockIdx.z;
    const int v0  = blockIdx.y * 128;
    const int n0  = blockIdx.x * 128;
    const int lr  = tid >> 2;          // 0..63 (row within half-tile)
    const int lc  = (tid & 3) * 4;     // 0,4,8,12 (float4 col within BK=16)
    const int tx  = tid & 15;
    const int ty  = tid >> 4;

    const float* wf = w1 + f * EMB;

    float acc[8][8];
#pragma unroll
    for (int i = 0; i < 8; i++)
#pragma unroll
        for (int j = 0; j < 8; j++) acc[i][j] = 0.f;

    float4 ar[2], br[2];

    // ---- prologue: load tile 0 ----
#pragma unroll
    for (int i = 0; i < 2; i++) {
        const int m = lr + i * 64;
        int v = v0 + m; if (v >= VOCAB) v = VOCAB - 1;   // clamp (stores guarded)
        ar[i] = __ldg((const float4*)(emb2 + (size_t)v * EMB + lc));
        br[i] = __ldg((const float4*)(wf + (size_t)(n0 + m) * KDIM + lc));
    }
#pragma unroll
    for (int i = 0; i < 2; i++) {
        const int m = lr + i * 64;
        As[0][lc + 0][m] = ar[i].x; As[0][lc + 1][m] = ar[i].y;
        As[0][lc + 2][m] = ar[i].z; As[0][lc + 3][m] = ar[i].w;
        Bs[0][lc + 0][m] = br[i].x; Bs[0][lc + 1][m] = br[i].y;
        Bs[0][lc + 2][m] = br[i].z; Bs[0][lc + 3][m] = br[i].w;
    }
    __syncthreads();

    const int T = EMB / 16;   // 8
#pragma unroll
    for (int t = 0; t < T; t++) {
        const int cur = t & 1;

        // issue next-tile global loads (latency overlapped with compute below)
        if (t + 1 < T) {
            const int k0 = (t + 1) * 16;
#pragma unroll
            for (int i = 0; i < 2; i++) {
                const int m = lr + i * 64;
                int v = v0 + m; if (v >= VOCAB) v = VOCAB - 1;
                ar[i] = __ldg((const float4*)(emb2 + (size_t)v * EMB + k0 + lc));
                br[i] = __ldg((const float4*)(wf + (size_t)(n0 + m) * KDIM + k0 + lc));
            }
        }

        // compute on current buffer
#pragma unroll
        for (int kk = 0; kk < 16; kk++) {
            const float4 aA = *(const float4*)&As[cur][kk][ty * 4];
            const float4 aB = *(const float4*)&As[cur][kk][ty * 4 + 64];
            const float4 bA = *(const float4*)&Bs[cur][kk][tx * 4];
            const float4 bB = *(const float4*)&Bs[cur][kk][tx * 4 + 64];
            const float a[8] = {aA.x, aA.y, aA.z, aA.w, aB.x, aB.y, aB.z, aB.w};
            const float b[8] = {bA.x, bA.y, bA.z, bA.w, bB.x, bB.y, bB.z, bB.w};
#pragma unroll
            for (int i = 0; i < 8; i++)
#pragma unroll
                for (int j = 0; j < 8; j++)
                    acc[i][j] = fmaf(a[i], b[j], acc[i][j]);
        }

        // stage next tile (buf^1 last read at t-1; barrier at end of t-1 covers WAR)
        if (t + 1 < T) {
            const int nxt = cur ^ 1;
#pragma unroll
            for (int i = 0; i < 2; i++) {
                const int m = lr + i * 64;
                As[nxt][lc + 0][m] = ar[i].x; As[nxt][lc + 1][m] = ar[i].y;
                As[nxt][lc + 2][m] = ar[i].z; As[nxt][lc + 3][m] = ar[i].w;
                Bs[nxt][lc + 0][m] = br[i].x; Bs[nxt][lc + 1][m] = br[i].y;
                Bs[nxt][lc + 2][m] = br[i].z; Bs[nxt][lc + 3][m] = br[i].w;
            }
            __syncthreads();
        }
    }

    float* Pf = g_P + (size_t)f * VOCAB * HID;
#pragma unroll
    for (int i = 0; i < 8; i++) {
        const int vm = (i < 4) ? (ty * 4 + i) : (64 + ty * 4 + i - 4);
        const int v  = v0 + vm;
        if (v < VOCAB) {
            float* outp = Pf + (size_t)v * HID + n0;
            float4 o;
            o.x = acc[i][0]; o.y = acc[i][1]; o.z = acc[i][2]; o.w = acc[i][3];
            *(float4*)(outp + tx * 4) = o;
            o.x = acc[i][4]; o.y = acc[i][5]; o.z = acc[i][6]; o.w = acc[i][7];
            *(float4*)(outp + 64 + tx * 4) = o;
        }
    }
}

// ---------------------------------------------------------------------------
// Kernel 3: h1[b,n] = relu( sum_f P[f][idx[b,f]][n] ).
// 4 samples per block, 64 threads per sample, float4 columns:
// 26 independent 16B loads per thread -> high MLP, 4x fewer LDG than scalar.
// ---------------------------------------------------------------------------
__global__ __launch_bounds__(256)
void gather_sum_relu_kernel(const int* __restrict__ sparse,
                            float* __restrict__ h1)
{
    const int tid  = threadIdx.x;
    const int slot = tid >> 6;              // 0..3 : sample within block
    const int c4   = (tid & 63) * 4;        // column base (float4)
    const int b    = blockIdx.x * 4 + slot;

    __shared__ int sidx[4][NS];
    if (tid < 4 * NS)
        sidx[tid / NS][tid % NS] = sparse[(blockIdx.x * 4 + tid / NS) * NS + (tid % NS)];
    __syncthreads();

    float4 sum = make_float4(0.f, 0.f, 0.f, 0.f);
#pragma unroll
    for (int f = 0; f < NS; f++) {
        const float4 v = __ldg((const float4*)(g_P + ((size_t)f * VOCAB + sidx[slot][f]) * HID + c4));
        sum.x += v.x; sum.y += v.y; sum.z += v.z; sum.w += v.w;
    }
    float4 o;
    o.x = fmaxf(sum.x, 0.f); o.y = fmaxf(sum.y, 0.f);
    o.z = fmaxf(sum.z, 0.f); o.w = fmaxf(sum.w, 0.f);
    *(float4*)(h1 + (size_t)b * HID + c4) = o;
}

// ---------------------------------------------------------------------------
// Kernel 4: double-buffered SGEMM + ReLU, layer 2: h2 = relu(h1 @ w2^T)
// Block tile 128x128, BK=16, 256 threads, 8x8 per thread, one sync/tile.
// ---------------------------------------------------------------------------
template <int K>
__global__ __launch_bounds__(256, 2)
void gemm_relu_kernel(const float* __restrict__ A,   // [BATCH, K]
                      const float* __restrict__ W,   // [HID, K] row-major
                      float* __restrict__ C)         // [BATCH, HID]
{
    __shared__ float As[2][16][128];
    __shared__ float Bs[2][16][128];

    const int tid = threadIdx.x;
    const int m0  = blockIdx.y * 128;
    const int n0  = blockIdx.x * 128;
    const int lr  = tid >> 2;          // 0..63
    const int lc  = (tid & 3) * 4;     // 0,4,8,12
    const int tx  = tid & 15;
    const int ty  = tid >> 4;

    float acc[8][8];
#pragma unroll
    for (int i = 0; i < 8; i++)
#pragma unroll
        for (int j = 0; j < 8; j++) acc[i][j] = 0.f;

    float4 ar[2], br[2];

#pragma unroll
    for (int i = 0; i < 2; i++) {
        const int m = lr + i * 64;
        ar[i] = __ldg((const float4*)(A + (size_t)(m0 + m) * K + lc));
        br[i] = __ldg((const float4*)(W + (size_t)(n0 + m) * K + lc));
    }
#pragma unroll
    for (int i = 0; i < 2; i++) {
        const int m = lr + i * 64;
        As[0][lc + 0][m] = ar[i].x; As[0][lc + 1][m] = ar[i].y;
        As[0][lc + 2][m] = ar[i].z; As[0][lc + 3][m] = ar[i].w;
        Bs[0][lc + 0][m] = br[i].x; Bs[0][lc + 1][m] = br[i].y;
        Bs[0][lc + 2][m] = br[i].z; Bs[0][lc + 3][m] = br[i].w;
    }
    __syncthreads();

    const int T = K / 16;
#pragma unroll 4
    for (int t = 0; t < T; t++) {
        const int cur = t & 1;

        if (t + 1 < T) {
            const int k0 = (t + 1) * 16;
#pragma unroll
            for (int i = 0; i < 2; i++) {
                const int m = lr + i * 64;
                ar[i] = __ldg((const float4*)(A + (size_t)(m0 + m) * K + k0 + lc));
                br[i] = __ldg((const float4*)(W + (size_t)(n0 + m) * K + k0 + lc));
            }
        }

#pragma unroll
        for (int kk = 0; kk < 16; kk++) {
            const float4 aA = *(const float4*)&As[cur][kk][ty * 4];
            const float4 aB = *(const float4*)&As[cur][kk][ty * 4 + 64];
            const float4 bA = *(const float4*)&Bs[cur][kk][tx * 4];
            const float4 bB = *(const float4*)&Bs[cur][kk][tx * 4 + 64];
            const float a[8] = {aA.x, aA.y, aA.z, aA.w, aB.x, aB.y, aB.z, aB.w};
            const float b[8] = {bA.x, bA.y, bA.z, bA.w, bB.x, bB.y, bB.z, bB.w};
#pragma unroll
            for (int i = 0; i < 8; i++)
#pragma unroll
                for (int j = 0; j < 8; j++)
                    acc[i][j] = fmaf(a[i], b[j], acc[i][j]);
        }

        if (t + 1 < T) {
            const int nxt = cur ^ 1;
#pragma unroll
            for (int i = 0; i < 2; i++) {
                const int m = lr + i * 64;
                As[nxt][lc + 0][m] = ar[i].x; As[nxt][lc + 1][m] = ar[i].y;
                As[nxt][lc + 2][m] = ar[i].z; As[nxt][lc + 3][m] = ar[i].w;
                Bs[nxt][lc + 0][m] = br[i].x; Bs[nxt][lc + 1][m] = br[i].y;
                Bs[nxt][lc + 2][m] = br[i].z; Bs[nxt][lc + 3][m] = br[i].w;
            }
            __syncthreads();
        }
    }

#pragma unroll
    for (int i = 0; i < 8; i++) {
        const int row = m0 + ((i < 4) ? (ty * 4 + i) : (64 + ty * 4 + i - 4));
        float* outp = C + (size_t)row * HID + n0;
        float4 v;
        v.x = fmaxf(acc[i][0], 0.f); v.y = fmaxf(acc[i][1], 0.f);
        v.z = fmaxf(acc[i][2], 0.f); v.w = fmaxf(acc[i][3], 0.f);
        *(float4*)(outp + tx * 4) = v;
        v.x = fmaxf(acc[i][4], 0.f); v.y = fmaxf(acc[i][5], 0.f);
        v.z = fmaxf(acc[i][6], 0.f); v.w = fmaxf(acc[i][7], 0.f);
        *(float4*)(outp + 64 + tx * 4) = v;
    }
}

// ---------------------------------------------------------------------------
// Kernel 5: y3 = h2 . w3, out = sigmoid(y12 + y3). One warp per sample.
// ---------------------------------------------------------------------------
__global__ void final_kernel(const float* __restrict__ w3, float* __restrict__ out)
{
    const int warp = threadIdx.x >> 5;
    const int lane = threadIdx.x & 31;
    const int i    = blockIdx.x * 8 + warp;
    const float* h = g_h2 + (size_t)i * HID;

    float sum = 0.f;
#pragma unroll
    for (int t = 0; t < 8; t++) {
        const int j = lane + t * 32;
        sum = fmaf(h[j], w3[j], sum);
    }
#pragma unroll
    for (int off = 16; off; off >>= 1)
        sum += __shfl_down_sync(0xffffffffu, sum, off);

    if (lane == 0) {
        const float x = g_y12[i] + sum;
        out[i] = 1.f / (1.f + expf(-x));
    }
}

// ---------------------------------------------------------------------------
extern "C" void kernel_launch(void* const* d_in, const int* in_sizes, int n_in,
                              void* d_out, int out_size)
{
    const float* dense  = (const float*)d_in[0];
    const int*   sparse = (const int*)  d_in[1];
    const float* emb1   = (const float*)d_in[2];
    const float* emb2   = (const float*)d_in[3];
    const float* fm_w   = (const float*)d_in[4];
    const float* w1     = (const float*)d_in[5];
    const float* w2     = (const float*)d_in[6];
    const float* w3     = (const float*)d_in[7];
    float* out = (float*)d_out;

    void *p1 = nullptr, *p2 = nullptr;
    cudaGetSymbolAddress(&p1, g_h1);   // capture-safe host query, no allocation
    cudaGetSymbolAddress(&p2, g_h2);
    float* h1 = (float*)p1;
    float* h2 = (float*)p2;

    fm_kernel<<<BATCH, 128>>>(dense, sparse, emb1, emb2, fm_w);

    // P[f] = emb2 @ W1_f^T : grid (n-tiles=2, v-tiles=ceil(4823/128)=38, f=26)
    dim3 pgrid(HID / 128, (VOCAB + 127) / 128, NS);
    precompute_P_kernel<<<pgrid, 256>>>(emb2, w1);

    gather_sum_relu_kernel<<<BATCH / 4, 256>>>(sparse, h1);

    dim3 grid(HID / 128, BATCH / 128);   // (2, 128)
    gemm_relu_kernel<HID><<<grid, 256>>>(h1, w2, h2);

    final_kernel<<<BATCH / 8, 256>>>(w3, out);
}

// round 9
// speedup vs baseline: 2.8658x; 2.8658x over previous
#include <cuda_runtime.h>
#include <cuda_bf16.h>
#include <math.h>
#include <stdint.h>

#define BATCH 16384
#define NS 26
#define ND 13
#define EMB 128
#define KDIM 3328   // NS * EMB
#define HID 256
#define VOCAB 4823

// Scratch (device globals; no allocations allowed)
__device__ __nv_bfloat16 g_Ph[(size_t)NS * VOCAB * HID];  // 64.2 MB bf16 P
__device__ __nv_bfloat16 g_emb2h[VOCAB * EMB];
__device__ __nv_bfloat16 g_w1h[HID * KDIM];
__device__ __nv_bfloat16 g_w2h[HID * HID];
__device__ __nv_bfloat16 g_h1h[(size_t)BATCH * HID];
__device__ float         g_h2[(size_t)BATCH * HID];
__device__ float         g_y12[BATCH];

// ---------------------------------------------------------------------------
// MMA helpers (bf16 m16n8k16, fp32 accum; TN layout, no trans needed)
// ---------------------------------------------------------------------------
__device__ __forceinline__ void ldsm4(uint32_t* r, uint32_t addr) {
    asm volatile("ldmatrix.sync.aligned.m8n8.x4.shared.b16 {%0,%1,%2,%3}, [%4];"
                 : "=r"(r[0]), "=r"(r[1]), "=r"(r[2]), "=r"(r[3]) : "r"(addr));
}
__device__ __forceinline__ void mma16816(float* c, const uint32_t* a, const uint32_t* b) {
    asm volatile("mma.sync.aligned.m16n8k16.row.col.f32.bf16.bf16.f32 "
                 "{%0,%1,%2,%3}, {%4,%5,%6,%7}, {%8,%9}, {%0,%1,%2,%3};"
                 : "+f"(c[0]), "+f"(c[1]), "+f"(c[2]), "+f"(c[3])
                 : "r"(a[0]), "r"(a[1]), "r"(a[2]), "r"(a[3]), "r"(b[0]), "r"(b[1]));
}
__device__ __forceinline__ uint32_t smem_u32(const void* p) {
    return (uint32_t)__cvta_generic_to_shared(p);
}

// ---------------------------------------------------------------------------
// Kernel 0: fp32 -> bf16 conversion of emb2, w1, w2 (one pass, float4 wide)
// ---------------------------------------------------------------------------
__global__ void convert_bf16_kernel(const float* __restrict__ emb2,
                                    const float* __restrict__ w1,
                                    const float* __restrict__ w2)
{
    const int n0 = VOCAB * EMB / 4, n1 = HID * KDIM / 4, n2 = HID * HID / 4;
    int i = blockIdx.x * blockDim.x + threadIdx.x;
    const float* src; __nv_bfloat16* dst; int j;
    if      (i < n0)           { src = emb2; dst = g_emb2h; j = i; }
    else if (i < n0 + n1)      { src = w1;   dst = g_w1h;   j = i - n0; }
    else if (i < n0 + n1 + n2) { src = w2;   dst = g_w2h;   j = i - n0 - n1; }
    else return;
    const float4 v = __ldg((const float4*)src + j);
    __nv_bfloat162* d = (__nv_bfloat162*)dst + (size_t)j * 2;
    d[0] = __floats2bfloat162_rn(v.x, v.y);
    d[1] = __floats2bfloat162_rn(v.z, v.w);
}

// ---------------------------------------------------------------------------
// Kernel 1: first + second order FM terms (kept exact fp32).
// ---------------------------------------------------------------------------
__global__ void fm_kernel(const float* __restrict__ dense,
                          const int*   __restrict__ sparse,
                          const float* __restrict__ emb1,
                          const float* __restrict__ emb2,
                          const float* __restrict__ fm_w)
{
    const int i   = blockIdx.x;
    const int tid = threadIdx.x;
    __shared__ int   sidx[NS];
    __shared__ float wsum[4];

    if (tid < NS) sidx[tid] = sparse[i * NS + tid];
    __syncthreads();

    float s = 0.f, ss = 0.f;
#pragma unroll
    for (int f = 0; f < NS; f++) {
        const float v = __ldg(emb2 + (size_t)sidx[f] * EMB + tid);
        s += v; ss += v * v;
    }
    float val = 0.5f * (s * s - ss);
    if (tid < NS) val += __ldg(emb1 + sidx[tid]);
    if (tid < ND) val += dense[i * ND + tid] * fm_w[tid];

#pragma unroll
    for (int off = 16; off; off >>= 1)
        val += __shfl_down_sync(0xffffffffu, val, off);
    if ((tid & 31) == 0) wsum[tid >> 5] = val;
    __syncthreads();
    if (tid == 0) g_y12[i] = wsum[0] + wsum[1] + wsum[2] + wsum[3];
}

// ---------------------------------------------------------------------------
// Kernel 2: precompute P[f][v][n] = sum_e emb2[v,e]*w1[n,f*128+e]  (bf16 MMA)
// 26 GEMMs [4823,128]@[128,256]. Block 128x128, BK=32, 8 warps (4Mx2N),
// warp tile 32x64, double-buffered smem (reg-staged), output bf16.
// Staging: 2 threads/row, 16 bf16 (= 2 x uint4) per thread -> full 32-col tile.
// ---------------------------------------------------------------------------
__global__ __launch_bounds__(256, 2)
void precompute_P_mma(void)
{
    __shared__ __align__(16) __nv_bfloat16 As[2][128][40];   // 80B stride: ldmatrix conflict-free
    __shared__ __align__(16) __nv_bfloat16 Bs[2][128][40];

    const int tid  = threadIdx.x;
    const int f    = blockIdx.z;
    const int v0   = blockIdx.y * 128;
    const int n0   = blockIdx.x * 128;
    const int wid  = tid >> 5, lane = tid & 31;
    const int warpM = wid & 3, warpN = wid >> 2;

    const int lrow = tid >> 1;           // 0..127
    const int lk   = (tid & 1) << 4;     // 0 or 16 (element offset; thread covers 16 bf16)

    const __nv_bfloat16* __restrict__ embh = g_emb2h;
    const __nv_bfloat16* __restrict__ w1h  = g_w1h;

    int arow = v0 + lrow; if (arow >= VOCAB) arow = VOCAB - 1;   // clamp
    const __nv_bfloat16* aptr = embh + (size_t)arow * EMB + lk;
    const __nv_bfloat16* bptr = w1h + (size_t)(n0 + lrow) * KDIM + f * EMB + lk;

    float acc[2][8][4];
#pragma unroll
    for (int mt = 0; mt < 2; mt++)
#pragma unroll
        for (int nt = 0; nt < 8; nt++)
#pragma unroll
            for (int q = 0; q < 4; q++) acc[mt][nt][q] = 0.f;

    uint4 a0 = *(const uint4*)aptr, a1 = *(const uint4*)(aptr + 8);
    uint4 b0 = *(const uint4*)bptr, b1 = *(const uint4*)(bptr + 8);
    *(uint4*)&As[0][lrow][lk]     = a0; *(uint4*)&As[0][lrow][lk + 8] = a1;
    *(uint4*)&Bs[0][lrow][lk]     = b0; *(uint4*)&Bs[0][lrow][lk + 8] = b1;
    __syncthreads();

    const int T = EMB / 32;   // 4
#pragma unroll
    for (int t = 0; t < T; t++) {
        const int cur = t & 1;
        if (t + 1 < T) {
            a0 = *(const uint4*)(aptr + (t + 1) * 32);
            a1 = *(const uint4*)(aptr + (t + 1) * 32 + 8);
            b0 = *(const uint4*)(bptr + (t + 1) * 32);
            b1 = *(const uint4*)(bptr + (t + 1) * 32 + 8);
        }
#pragma unroll
        for (int kk = 0; kk < 2; kk++) {
            const int k = kk * 16;
            uint32_t a[2][4];
#pragma unroll
            for (int mt = 0; mt < 2; mt++)
                ldsm4(a[mt], smem_u32(&As[cur][warpM * 32 + mt * 16 + (lane & 15)]
                                         [k + ((lane >> 4) << 3)]));
            uint32_t b[8][2];
#pragma unroll
            for (int nt2 = 0; nt2 < 4; nt2++) {
                uint32_t r[4];
                ldsm4(r, smem_u32(&Bs[cur][warpN * 64 + nt2 * 16 + (lane & 7) + ((lane >> 4) << 3)]
                                     [k + (((lane >> 3) & 1) << 3)]));
                b[2 * nt2][0] = r[0]; b[2 * nt2][1] = r[1];
                b[2 * nt2 + 1][0] = r[2]; b[2 * nt2 + 1][1] = r[3];
            }
#pragma unroll
            for (int mt = 0; mt < 2; mt++)
#pragma unroll
                for (int nt = 0; nt < 8; nt++)
                    mma16816(acc[mt][nt], a[mt], b[nt]);
        }
        if (t + 1 < T) {
            const int nxt = cur ^ 1;
            *(uint4*)&As[nxt][lrow][lk]     = a0; *(uint4*)&As[nxt][lrow][lk + 8] = a1;
            *(uint4*)&Bs[nxt][lrow][lk]     = b0; *(uint4*)&Bs[nxt][lrow][lk + 8] = b1;
            __syncthreads();
        }
    }

    __nv_bfloat16* Pf = g_Ph + (size_t)f * VOCAB * HID;
    const int g  = lane >> 2;
    const int t4 = lane & 3;
#pragma unroll
    for (int mt = 0; mt < 2; mt++) {
        const int r0 = v0 + warpM * 32 + mt * 16 + g;
#pragma unroll
        for (int nt = 0; nt < 8; nt++) {
            const int col = n0 + warpN * 64 + nt * 8 + 2 * t4;
            if (r0 < VOCAB)
                *(__nv_bfloat162*)(Pf + (size_t)r0 * HID + col) =
                    __floats2bfloat162_rn(acc[mt][nt][0], acc[mt][nt][1]);
            if (r0 + 8 < VOCAB)
                *(__nv_bfloat162*)(Pf + (size_t)(r0 + 8) * HID + col) =
                    __floats2bfloat162_rn(acc[mt][nt][2], acc[mt][nt][3]);
        }
    }
}

// ---------------------------------------------------------------------------
// Kernel 3: h1[b,n] = relu( sum_f P_bf16[f][idx[b,f]][n] ), fp32 accum,
// bf16 output. 8 samples/block, 32 threads/sample, 16B loads (8 bf16).
// ---------------------------------------------------------------------------
__global__ __launch_bounds__(256)
void gather_sum_relu_kernel(const int* __restrict__ sparse)
{
    const int tid  = threadIdx.x;
    const int slot = tid >> 5;            // 0..7
    const int lane = tid & 31;
    const int b    = blockIdx.x * 8 + slot;
    const int c    = lane * 8;            // column base (8 bf16)

    __shared__ int sidx[8][NS];
    if (tid < 8 * NS)
        sidx[tid / NS][tid % NS] = sparse[(blockIdx.x * 8 + tid / NS) * NS + (tid % NS)];
    __syncthreads();

    const __nv_bfloat16* __restrict__ Ph = g_Ph;

    float s[8];
#pragma unroll
    for (int q = 0; q < 8; q++) s[q] = 0.f;

#pragma unroll
    for (int f = 0; f < NS; f++) {
        const uint4 u = __ldg((const uint4*)(Ph + ((size_t)f * VOCAB + sidx[slot][f]) * HID + c));
        const __nv_bfloat162* p = (const __nv_bfloat162*)&u;
#pragma unroll
        for (int j = 0; j < 4; j++) {
            const float2 v = __bfloat1622float2(p[j]);
            s[2 * j] += v.x; s[2 * j + 1] += v.y;
        }
    }
    __nv_bfloat162 o[4];
#pragma unroll
    for (int j = 0; j < 4; j++)
        o[j] = __floats2bfloat162_rn(fmaxf(s[2 * j], 0.f), fmaxf(s[2 * j + 1], 0.f));
    *(uint4*)(g_h1h + (size_t)b * HID + c) = *(uint4*)o;
}

// ---------------------------------------------------------------------------
// Kernel 4: layer 2 bf16 MMA: h2 = relu(h1 @ w2^T), fp32 output.
// Same tile scheme as precompute; K=256, no bounds handling needed.
// ---------------------------------------------------------------------------
__global__ __launch_bounds__(256, 2)
void gemm2_mma(void)
{
    __shared__ __align__(16) __nv_bfloat16 As[2][128][40];
    __shared__ __align__(16) __nv_bfloat16 Bs[2][128][40];

    const int tid  = threadIdx.x;
    const int m0   = blockIdx.y * 128;
    const int n0   = blockIdx.x * 128;
    const int wid  = tid >> 5, lane = tid & 31;
    const int warpM = wid & 3, warpN = wid >> 2;

    const int lrow = tid >> 1;
    const int lk   = (tid & 1) << 4;

    const __nv_bfloat16* __restrict__ h1h = g_h1h;
    const __nv_bfloat16* __restrict__ w2h = g_w2h;

    const __nv_bfloat16* aptr = h1h + (size_t)(m0 + lrow) * HID + lk;
    const __nv_bfloat16* bptr = w2h + (size_t)(n0 + lrow) * HID + lk;

    float acc[2][8][4];
#pragma unroll
    for (int mt = 0; mt < 2; mt++)
#pragma unroll
        for (int nt = 0; nt < 8; nt++)
#pragma unroll
            for (int q = 0; q < 4; q++) acc[mt][nt][q] = 0.f;

    uint4 a0 = *(const uint4*)aptr, a1 = *(const uint4*)(aptr + 8);
    uint4 b0 = *(const uint4*)bptr, b1 = *(const uint4*)(bptr + 8);
    *(uint4*)&As[0][lrow][lk]     = a0; *(uint4*)&As[0][lrow][lk + 8] = a1;
    *(uint4*)&Bs[0][lrow][lk]     = b0; *(uint4*)&Bs[0][lrow][lk + 8] = b1;
    __syncthreads();

    const int T = HID / 32;   // 8
#pragma unroll
    for (int t = 0; t < T; t++) {
        const int cur = t & 1;
        if (t + 1 < T) {
            a0 = *(const uint4*)(aptr + (t + 1) * 32);
            a1 = *(const uint4*)(aptr + (t + 1) * 32 + 8);
            b0 = *(const uint4*)(bptr + (t + 1) * 32);
            b1 = *(const uint4*)(bptr + (t + 1) * 32 + 8);
        }
#pragma unroll
        for (int kk = 0; kk < 2; kk++) {
            const int k = kk * 16;
            uint32_t a[2][4];
#pragma unroll
            for (int mt = 0; mt < 2; mt++)
                ldsm4(a[mt], smem_u32(&As[cur][warpM * 32 + mt * 16 + (lane & 15)]
                                         [k + ((lane >> 4) << 3)]));
            uint32_t b[8][2];
#pragma unroll
            for (int nt2 = 0; nt2 < 4; nt2++) {
                uint32_t r[4];
                ldsm4(r, smem_u32(&Bs[cur][warpN * 64 + nt2 * 16 + (lane & 7) + ((lane >> 4) << 3)]
                                     [k + (((lane >> 3) & 1) << 3)]));
                b[2 * nt2][0] = r[0]; b[2 * nt2][1] = r[1];
                b[2 * nt2 + 1][0] = r[2]; b[2 * nt2 + 1][1] = r[3];
            }
#pragma unroll
            for (int mt = 0; mt < 2; mt++)
#pragma unroll
                for (int nt = 0; nt < 8; nt++)
                    mma16816(acc[mt][nt], a[mt], b[nt]);
        }
        if (t + 1 < T) {
            const int nxt = cur ^ 1;
            *(uint4*)&As[nxt][lrow][lk]     = a0; *(uint4*)&As[nxt][lrow][lk + 8] = a1;
            *(uint4*)&Bs[nxt][lrow][lk]     = b0; *(uint4*)&Bs[nxt][lrow][lk + 8] = b1;
            __syncthreads();
        }
    }

    const int g  = lane >> 2;
    const int t4 = lane & 3;
#pragma unroll
    for (int mt = 0; mt < 2; mt++) {
        const int r0 = m0 + warpM * 32 + mt * 16 + g;
#pragma unroll
        for (int nt = 0; nt < 8; nt++) {
            const int col = n0 + warpN * 64 + nt * 8 + 2 * t4;
            float2 v0 = make_float2(fmaxf(acc[mt][nt][0], 0.f), fmaxf(acc[mt][nt][1], 0.f));
            float2 v1 = make_float2(fmaxf(acc[mt][nt][2], 0.f), fmaxf(acc[mt][nt][3], 0.f));
            *(float2*)(g_h2 + (size_t)r0 * HID + col)       = v0;
            *(float2*)(g_h2 + (size_t)(r0 + 8) * HID + col) = v1;
        }
    }
}

// ---------------------------------------------------------------------------
// Kernel 5: y3 = h2 . w3, out = sigmoid(y12 + y3). One warp per sample.
// ---------------------------------------------------------------------------
__global__ void final_kernel(const float* __restrict__ w3, float* __restrict__ out)
{
    const int warp = threadIdx.x >> 5;
    const int lane = threadIdx.x & 31;
    const int i    = blockIdx.x * 8 + warp;
    const float* h = g_h2 + (size_t)i * HID;

    float sum = 0.f;
#pragma unroll
    for (int t = 0; t < 8; t++) {
        const int j = lane + t * 32;
        sum = fmaf(h[j], w3[j], sum);
    }
#pragma unroll
    for (int off = 16; off; off >>= 1)
        sum += __shfl_down_sync(0xffffffffu, sum, off);

    if (lane == 0) {
        const float x = g_y12[i] + sum;
        out[i] = 1.f / (1.f + expf(-x));
    }
}

// ---------------------------------------------------------------------------
extern "C" void kernel_launch(void* const* d_in, const int* in_sizes, int n_in,
                              void* d_out, int out_size)
{
    const float* dense  = (const float*)d_in[0];
    const int*   sparse = (const int*)  d_in[1];
    const float* emb1   = (const float*)d_in[2];
    const float* emb2   = (const float*)d_in[3];
    const float* fm_w   = (const float*)d_in[4];
    const float* w1     = (const float*)d_in[5];
    const float* w2     = (const float*)d_in[6];
    const float* w3     = (const float*)d_in[7];
    float* out = (float*)d_out;

    const int nconv = (VOCAB * EMB + HID * KDIM + HID * HID) / 4;
    convert_bf16_kernel<<<(nconv + 255) / 256, 256>>>(emb2, w1, w2);

    fm_kernel<<<BATCH, 128>>>(dense, sparse, emb1, emb2, fm_w);

    dim3 pgrid(HID / 128, (VOCAB + 127) / 128, NS);   // (2, 38, 26)
    precompute_P_mma<<<pgrid, 256>>>();

    gather_sum_relu_kernel<<<BATCH / 8, 256>>>(sparse);

    dim3 grid2(HID / 128, BATCH / 128);               // (2, 128)
    gemm2_mma<<<grid2, 256>>>();

    final_kernel<<<BATCH / 8, 256>>>(w3, out);
}

// round 12
// speedup vs baseline: 3.1445x; 1.0973x over previous
#include <cuda_runtime.h>
#include <cuda_bf16.h>
#include <math.h>
#include <stdint.h>

#define BATCH 16384
#define NS 26
#define ND 13
#define EMB 128
#define KDIM 3328   // NS * EMB
#define HID 256
#define VOCAB 4823

// Scratch (device globals; no allocations allowed)
__device__ __nv_bfloat16 g_Ph[(size_t)NS * VOCAB * HID];  // 64.2 MB bf16 P
__device__ __nv_bfloat16 g_emb2h[VOCAB * EMB];
__device__ __nv_bfloat16 g_w1h[HID * KDIM];
__device__ __nv_bfloat16 g_w2h[HID * HID];
__device__ __nv_bfloat16 g_h1h[(size_t)BATCH * HID];
__device__ float         g_h2[(size_t)BATCH * HID];
__device__ float         g_y12[BATCH];

// ---------------------------------------------------------------------------
// MMA helpers (bf16 m16n8k16, fp32 accum; TN layout, no trans needed)
// ---------------------------------------------------------------------------
__device__ __forceinline__ void ldsm4(uint32_t* r, uint32_t addr) {
    asm volatile("ldmatrix.sync.aligned.m8n8.x4.shared.b16 {%0,%1,%2,%3}, [%4];"
                 : "=r"(r[0]), "=r"(r[1]), "=r"(r[2]), "=r"(r[3]) : "r"(addr));
}
__device__ __forceinline__ void mma16816(float* c, const uint32_t* a, const uint32_t* b) {
    asm volatile("mma.sync.aligned.m16n8k16.row.col.f32.bf16.bf16.f32 "
                 "{%0,%1,%2,%3}, {%4,%5,%6,%7}, {%8,%9}, {%0,%1,%2,%3};"
                 : "+f"(c[0]), "+f"(c[1]), "+f"(c[2]), "+f"(c[3])
                 : "r"(a[0]), "r"(a[1]), "r"(a[2]), "r"(a[3]), "r"(b[0]), "r"(b[1]));
}
__device__ __forceinline__ uint32_t smem_u32(const void* p) {
    return (uint32_t)__cvta_generic_to_shared(p);
}

// ---------------------------------------------------------------------------
// Kernel 0: fp32 -> bf16 conversion of emb2, w1, w2 (one pass, float4 wide)
// ---------------------------------------------------------------------------
__global__ void convert_bf16_kernel(const float* __restrict__ emb2,
                                    const float* __restrict__ w1,
                                    const float* __restrict__ w2)
{
    const int n0 = VOCAB * EMB / 4, n1 = HID * KDIM / 4, n2 = HID * HID / 4;
    int i = blockIdx.x * blockDim.x + threadIdx.x;
    const float* src; __nv_bfloat16* dst; int j;
    if      (i < n0)           { src = emb2; dst = g_emb2h; j = i; }
    else if (i < n0 + n1)      { src = w1;   dst = g_w1h;   j = i - n0; }
    else if (i < n0 + n1 + n2) { src = w2;   dst = g_w2h;   j = i - n0 - n1; }
    else return;
    const float4 v = __ldg((const float4*)src + j);
    __nv_bfloat162* d = (__nv_bfloat162*)dst + (size_t)j * 2;
    d[0] = __floats2bfloat162_rn(v.x, v.y);
    d[1] = __floats2bfloat162_rn(v.z, v.w);
}

// ---------------------------------------------------------------------------
// Kernel 2: precompute P[f][v][n] = sum_e emb2[v,e]*w1[n,f*128+e]  (bf16 MMA)
// 26 GEMMs [4823,128]@[128,256]. Block 128x128, BK=32, 8 warps (4Mx2N),
// warp tile 32x64, double-buffered smem (reg-staged), output bf16.
// Staging: 2 threads/row, 16 bf16 (= 2 x uint4) per thread -> full 32-col tile.
// ---------------------------------------------------------------------------
__global__ __launch_bounds__(256, 2)
void precompute_P_mma(void)
{
    __shared__ __align__(16) __nv_bfloat16 As[2][128][40];   // 80B stride: ldmatrix conflict-free
    __shared__ __align__(16) __nv_bfloat16 Bs[2][128][40];

    const int tid  = threadIdx.x;
    const int f    = blockIdx.z;
    const int v0   = blockIdx.y * 128;
    const int n0   = blockIdx.x * 128;
    const int wid  = tid >> 5, lane = tid & 31;
    const int warpM = wid & 3, warpN = wid >> 2;

    const int lrow = tid >> 1;           // 0..127
    const int lk   = (tid & 1) << 4;     // 0 or 16 (element offset; thread covers 16 bf16)

    const __nv_bfloat16* __restrict__ embh = g_emb2h;
    const __nv_bfloat16* __restrict__ w1h  = g_w1h;

    int arow = v0 + lrow; if (arow >= VOCAB) arow = VOCAB - 1;   // clamp
    const __nv_bfloat16* aptr = embh + (size_t)arow * EMB + lk;
    const __nv_bfloat16* bptr = w1h + (size_t)(n0 + lrow) * KDIM + f * EMB + lk;

    float acc[2][8][4];
#pragma unroll
    for (int mt = 0; mt < 2; mt++)
#pragma unroll
        for (int nt = 0; nt < 8; nt++)
#pragma unroll
            for (int q = 0; q < 4; q++) acc[mt][nt][q] = 0.f;

    uint4 a0 = *(const uint4*)aptr, a1 = *(const uint4*)(aptr + 8);
    uint4 b0 = *(const uint4*)bptr, b1 = *(const uint4*)(bptr + 8);
    *(uint4*)&As[0][lrow][lk]     = a0; *(uint4*)&As[0][lrow][lk + 8] = a1;
    *(uint4*)&Bs[0][lrow][lk]     = b0; *(uint4*)&Bs[0][lrow][lk + 8] = b1;
    __syncthreads();

    const int T = EMB / 32;   // 4
#pragma unroll
    for (int t = 0; t < T; t++) {
        const int cur = t & 1;
        if (t + 1 < T) {
            a0 = *(const uint4*)(aptr + (t + 1) * 32);
            a1 = *(const uint4*)(aptr + (t + 1) * 32 + 8);
            b0 = *(const uint4*)(bptr + (t + 1) * 32);
            b1 = *(const uint4*)(bptr + (t + 1) * 32 + 8);
        }
#pragma unroll
        for (int kk = 0; kk < 2; kk++) {
            const int k = kk * 16;
            uint32_t a[2][4];
#pragma unroll
            for (int mt = 0; mt < 2; mt++)
                ldsm4(a[mt], smem_u32(&As[cur][warpM * 32 + mt * 16 + (lane & 15)]
                                         [k + ((lane >> 4) << 3)]));
            uint32_t b[8][2];
#pragma unroll
            for (int nt2 = 0; nt2 < 4; nt2++) {
                uint32_t r[4];
                ldsm4(r, smem_u32(&Bs[cur][warpN * 64 + nt2 * 16 + (lane & 7) + ((lane >> 4) << 3)]
                                     [k + (((lane >> 3) & 1) << 3)]));
                b[2 * nt2][0] = r[0]; b[2 * nt2][1] = r[1];
                b[2 * nt2 + 1][0] = r[2]; b[2 * nt2 + 1][1] = r[3];
            }
#pragma unroll
            for (int mt = 0; mt < 2; mt++)
#pragma unroll
                for (int nt = 0; nt < 8; nt++)
                    mma16816(acc[mt][nt], a[mt], b[nt]);
        }
        if (t + 1 < T) {
            const int nxt = cur ^ 1;
            *(uint4*)&As[nxt][lrow][lk]     = a0; *(uint4*)&As[nxt][lrow][lk + 8] = a1;
            *(uint4*)&Bs[nxt][lrow][lk]     = b0; *(uint4*)&Bs[nxt][lrow][lk + 8] = b1;
            __syncthreads();
        }
    }

    __nv_bfloat16* Pf = g_Ph + (size_t)f * VOCAB * HID;
    const int g  = lane >> 2;
    const int t4 = lane & 3;
#pragma unroll
    for (int mt = 0; mt < 2; mt++) {
        const int r0 = v0 + warpM * 32 + mt * 16 + g;
#pragma unroll
        for (int nt = 0; nt < 8; nt++) {
            const int col = n0 + warpN * 64 + nt * 8 + 2 * t4;
            if (r0 < VOCAB)
                *(__nv_bfloat162*)(Pf + (size_t)r0 * HID + col) =
                    __floats2bfloat162_rn(acc[mt][nt][0], acc[mt][nt][1]);
            if (r0 + 8 < VOCAB)
                *(__nv_bfloat162*)(Pf + (size_t)(r0 + 8) * HID + col) =
                    __floats2bfloat162_rn(acc[mt][nt][2], acc[mt][nt][3]);
        }
    }
}

// ---------------------------------------------------------------------------
// Kernel 3 (FUSED fm + gather): per sample b,
//   y12[b] = fm first+second order terms (exact fp32 path)
//   h1[b,:] = relu( sum_f P_bf16[f][idx[b,f]][:] )  (fp32 accum, bf16 out)
// 8 samples/block, 32 lanes/sample. Each lane: 4 fp32 emb2 cols (fm) +
// 8 bf16 P cols (gather). Both row streams share one sidx load and issue
// 2 independent loads/iter -> doubled MLP against the same L2 latency.
// ---------------------------------------------------------------------------
__global__ __launch_bounds__(256)
void fm_gather_fused_kernel(const float* __restrict__ dense,
                            const int*   __restrict__ sparse,
                            const float* __restrict__ emb1,
                            const float* __restrict__ emb2,
                            const float* __restrict__ fm_w)
{
    const int tid  = threadIdx.x;
    const int slot = tid >> 5;            // 0..7
    const int lane = tid & 31;
    const int b    = blockIdx.x * 8 + slot;
    const int c4   = lane * 4;            // fm column base (float4)
    const int c8   = lane * 8;            // gather column base (8 bf16)

    __shared__ int sidx[8][NS];
    if (tid < 8 * NS)
        sidx[tid / NS][tid % NS] = sparse[(blockIdx.x * 8 + tid / NS) * NS + (tid % NS)];
    __syncthreads();

    const __nv_bfloat16* __restrict__ Ph = g_Ph;

    float4 s4  = make_float4(0.f, 0.f, 0.f, 0.f);
    float4 ss4 = make_float4(0.f, 0.f, 0.f, 0.f);
    float g[8];
#pragma unroll
    for (int q = 0; q < 8; q++) g[q] = 0.f;

#pragma unroll
    for (int f = 0; f < NS; f++) {
        const int idx = sidx[slot][f];
        const float4 e = __ldg((const float4*)(emb2 + (size_t)idx * EMB + c4));
        const uint4  u = __ldg((const uint4*)(Ph + ((size_t)f * VOCAB + idx) * HID + c8));

        s4.x += e.x; s4.y += e.y; s4.z += e.z; s4.w += e.w;
        ss4.x = fmaf(e.x, e.x, ss4.x); ss4.y = fmaf(e.y, e.y, ss4.y);
        ss4.z = fmaf(e.z, e.z, ss4.z); ss4.w = fmaf(e.w, e.w, ss4.w);

        const __nv_bfloat162* p = (const __nv_bfloat162*)&u;
#pragma unroll
        for (int j = 0; j < 4; j++) {
            const float2 v = __bfloat1622float2(p[j]);
            g[2 * j] += v.x; g[2 * j + 1] += v.y;
        }
    }

    // second-order FM partial (4 columns per lane)
    float val = 0.5f * ((s4.x * s4.x - ss4.x) + (s4.y * s4.y - ss4.y) +
                        (s4.z * s4.z - ss4.z) + (s4.w * s4.w - ss4.w));
    if (lane < NS) val += __ldg(emb1 + sidx[slot][lane]);          // first-order sparse
    if (lane < ND) val += dense[b * ND + lane] * fm_w[lane];       // first-order dense

#pragma unroll
    for (int off = 16; off; off >>= 1)
        val += __shfl_down_sync(0xffffffffu, val, off);
    if (lane == 0) g_y12[b] = val;

    __nv_bfloat162 o[4];
#pragma unroll
    for (int j = 0; j < 4; j++)
        o[j] = __floats2bfloat162_rn(fmaxf(g[2 * j], 0.f), fmaxf(g[2 * j + 1], 0.f));
    *(uint4*)(g_h1h + (size_t)b * HID + c8) = *(uint4*)o;
}

// ---------------------------------------------------------------------------
// Kernel 4: layer 2 bf16 MMA: h2 = relu(h1 @ w2^T), fp32 output.
// Same tile scheme as precompute; K=256, no bounds handling needed.
// ---------------------------------------------------------------------------
__global__ __launch_bounds__(256, 2)
void gemm2_mma(void)
{
    __shared__ __align__(16) __nv_bfloat16 As[2][128][40];
    __shared__ __align__(16) __nv_bfloat16 Bs[2][128][40];

    const int tid  = threadIdx.x;
    const int m0   = blockIdx.y * 128;
    const int n0   = blockIdx.x * 128;
    const int wid  = tid >> 5, lane = tid & 31;
    const int warpM = wid & 3, warpN = wid >> 2;

    const int lrow = tid >> 1;
    const int lk   = (tid & 1) << 4;

    const __nv_bfloat16* __restrict__ h1h = g_h1h;
    const __nv_bfloat16* __restrict__ w2h = g_w2h;

    const __nv_bfloat16* aptr = h1h + (size_t)(m0 + lrow) * HID + lk;
    const __nv_bfloat16* bptr = w2h + (size_t)(n0 + lrow) * HID + lk;

    float acc[2][8][4];
#pragma unroll
    for (int mt = 0; mt < 2; mt++)
#pragma unroll
        for (int nt = 0; nt < 8; nt++)
#pragma unroll
            for (int q = 0; q < 4; q++) acc[mt][nt][q] = 0.f;

    uint4 a0 = *(const uint4*)aptr, a1 = *(const uint4*)(aptr + 8);
    uint4 b0 = *(const uint4*)bptr, b1 = *(const uint4*)(bptr + 8);
    *(uint4*)&As[0][lrow][lk]     = a0; *(uint4*)&As[0][lrow][lk + 8] = a1;
    *(uint4*)&Bs[0][lrow][lk]     = b0; *(uint4*)&Bs[0][lrow][lk + 8] = b1;
    __syncthreads();

    const int T = HID / 32;   // 8
#pragma unroll
    for (int t = 0; t < T; t++) {
        const int cur = t & 1;
        if (t + 1 < T) {
            a0 = *(const uint4*)(aptr + (t + 1) * 32);
            a1 = *(const uint4*)(aptr + (t + 1) * 32 + 8);
            b0 = *(const uint4*)(bptr + (t + 1) * 32);
            b1 = *(const uint4*)(bptr + (t + 1) * 32 + 8);
        }
#pragma unroll
        for (int kk = 0; kk < 2; kk++) {
            const int k = kk * 16;
            uint32_t a[2][4];
#pragma unroll
            for (int mt = 0; mt < 2; mt++)
                ldsm4(a[mt], smem_u32(&As[cur][warpM * 32 + mt * 16 + (lane & 15)]
                                         [k + ((lane >> 4) << 3)]));
            uint32_t b[8][2];
#pragma unroll
            for (int nt2 = 0; nt2 < 4; nt2++) {
                uint32_t r[4];
                ldsm4(r, smem_u32(&Bs[cur][warpN * 64 + nt2 * 16 + (lane & 7) + ((lane >> 4) << 3)]
                                     [k + (((lane >> 3) & 1) << 3)]));
                b[2 * nt2][0] = r[0]; b[2 * nt2][1] = r[1];
                b[2 * nt2 + 1][0] = r[2]; b[2 * nt2 + 1][1] = r[3];
            }
#pragma unroll
            for (int mt = 0; mt < 2; mt++)
#pragma unroll
                for (int nt = 0; nt < 8; nt++)
                    mma16816(acc[mt][nt], a[mt], b[nt]);
        }
        if (t + 1 < T) {
            const int nxt = cur ^ 1;
            *(uint4*)&As[nxt][lrow][lk]     = a0; *(uint4*)&As[nxt][lrow][lk + 8] = a1;
            *(uint4*)&Bs[nxt][lrow][lk]     = b0; *(uint4*)&Bs[nxt][lrow][lk + 8] = b1;
            __syncthreads();
        }
    }

    const int g  = lane >> 2;
    const int t4 = lane & 3;
#pragma unroll
    for (int mt = 0; mt < 2; mt++) {
        const int r0 = m0 + warpM * 32 + mt * 16 + g;
#pragma unroll
        for (int nt = 0; nt < 8; nt++) {
            const int col = n0 + warpN * 64 + nt * 8 + 2 * t4;
            float2 v0 = make_float2(fmaxf(acc[mt][nt][0], 0.f), fmaxf(acc[mt][nt][1], 0.f));
            float2 v1 = make_float2(fmaxf(acc[mt][nt][2], 0.f), fmaxf(acc[mt][nt][3], 0.f));
            *(float2*)(g_h2 + (size_t)r0 * HID + col)       = v0;
            *(float2*)(g_h2 + (size_t)(r0 + 8) * HID + col) = v1;
        }
    }
}

// ---------------------------------------------------------------------------
// Kernel 5: y3 = h2 . w3, out = sigmoid(y12 + y3). One warp per sample.
// ---------------------------------------------------------------------------
__global__ void final_kernel(const float* __restrict__ w3, float* __restrict__ out)
{
    const int warp = threadIdx.x >> 5;
    const int lane = threadIdx.x & 31;
    const int i    = blockIdx.x * 8 + warp;
    const float* h = g_h2 + (size_t)i * HID;

    float sum = 0.f;
#pragma unroll
    for (int t = 0; t < 8; t++) {
        const int j = lane + t * 32;
        sum = fmaf(h[j], w3[j], sum);
    }
#pragma unroll
    for (int off = 16; off; off >>= 1)
        sum += __shfl_down_sync(0xffffffffu, sum, off);

    if (lane == 0) {
        const float x = g_y12[i] + sum;
        out[i] = 1.f / (1.f + expf(-x));
    }
}

// ---------------------------------------------------------------------------
extern "C" void kernel_launch(void* const* d_in, const int* in_sizes, int n_in,
                              void* d_out, int out_size)
{
    const float* dense  = (const float*)d_in[0];
    const int*   sparse = (const int*)  d_in[1];
    const float* emb1   = (const float*)d_in[2];
    const float* emb2   = (const float*)d_in[3];
    const float* fm_w   = (const float*)d_in[4];
    const float* w1     = (const float*)d_in[5];
    const float* w2     = (const float*)d_in[6];
    const float* w3     = (const float*)d_in[7];
    float* out = (float*)d_out;

    const int nconv = (VOCAB * EMB + HID * KDIM + HID * HID) / 4;
    convert_bf16_kernel<<<(nconv + 255) / 256, 256>>>(emb2, w1, w2);

    dim3 pgrid(HID / 128, (VOCAB + 127) / 128, NS);   // (2, 38, 26)
    precompute_P_mma<<<pgrid, 256>>>();

    fm_gather_fused_kernel<<<BATCH / 8, 256>>>(dense, sparse, emb1, emb2, fm_w);

    dim3 grid2(HID / 128, BATCH / 128);               // (2, 128)
    gemm2_mma<<<grid2, 256>>>();

    final_kernel<<<BATCH / 8, 256>>>(w3, out);
}